// round 11
// baseline (speedup 1.0000x reference)
#include <cuda_runtime.h>
#include <cstdint>

#define T_STEPS   8192
#define HID       1024
#define GATES     4096
#define REC_GRID  128
#define FULLMASK  0xffffffffu

// ---------------- scratch (static device globals; no allocations) ----------
__device__ float g_gates[(size_t)T_STEPS * GATES];   // 128 MB gate pre-activations

// h exchange records: 8 floats + tag, one 64B record per producer CTA,
// double-buffered by step parity. Tag t published at end of step t-1 means
// "h for step t is ready in this record".
struct __align__(64) HRec {
    float    h[8];       // offset 0..31
    unsigned tag;        // offset 32
    unsigned pad[7];
};
__device__ __align__(128) HRec g_hrec[2][REC_GRID];

// ---------------- strong-op primitives --------------------------------------
__device__ __forceinline__ unsigned ld_acquire_gpu(const unsigned* p) {
    unsigned v;
    asm volatile("ld.acquire.gpu.global.u32 %0, [%1];" : "=r"(v) : "l"(p) : "memory");
    return v;
}
__device__ __forceinline__ void st_release_gpu(unsigned* p, unsigned v) {
    asm volatile("st.release.gpu.global.u32 [%0], %1;" :: "l"(p), "r"(v) : "memory");
}
__device__ __forceinline__ void st_relaxed_v4(float* p, float4 v) {
    asm volatile("st.relaxed.gpu.global.v4.f32 [%0], {%1,%2,%3,%4};"
                 :: "l"(p), "f"(v.x), "f"(v.y), "f"(v.z), "f"(v.w) : "memory");
}
// L2-coherent weak load for the gates stream (written by the prior kernel).
__device__ __forceinline__ float ldcg_f(const float* p) {
    float v; asm volatile("ld.global.cg.f32 %0, [%1];" : "=f"(v) : "l"(p)); return v;
}

// Fast, accuracy-safe nonlinearities (rel err ~1e-6; budget 1e-3).
__device__ __forceinline__ float sigmoid_f(float x) {
    return __fdividef(1.f, 1.f + __expf(-x));
}
__device__ __forceinline__ float tanh_f(float x) {
    float xc = fminf(fmaxf(x, -15.f), 15.f);
    float e  = __expf(2.f * xc);
    return __fdividef(e - 1.f, e + 1.f);
}

// ======================= Kernel 1: gates_x GEMM =============================
// C[m,n] = sum_k x[m,k] * W_ih[n,k] + b_ih[n] + b_hh[n]
#define BM 128
#define BN 128
#define BK 8

__global__ __launch_bounds__(256) void gemm_gates_kernel(
    const float* __restrict__ x, const float* __restrict__ Wih,
    const float* __restrict__ b_ih, const float* __restrict__ b_hh)
{
    // Reset both buffers' record tags every replay (256 tags), stream-ordered
    // before the recurrence kernel.
    if (blockIdx.x == 0 && blockIdx.y == 0 && threadIdx.x < 2 * REC_GRID)
        g_hrec[threadIdx.x >> 7][threadIdx.x & 127].tag = 0u;

    __shared__ float As[BK][BM + 4];
    __shared__ float Bs[BK][BN + 4];

    const int tid  = threadIdx.x;
    const int arow = tid >> 1;
    const int acol = (tid & 1) << 2;
    const int trow = tid >> 4;
    const int tcol = tid & 15;

    const float* xg = x   + (size_t)(blockIdx.y * BM + arow) * 1024 + acol;
    const float* wg = Wih + (size_t)(blockIdx.x * BN + arow) * 1024 + acol;

    float acc[8][8];
#pragma unroll
    for (int i = 0; i < 8; i++)
#pragma unroll
        for (int j = 0; j < 8; j++) acc[i][j] = 0.f;

    for (int k0 = 0; k0 < 1024; k0 += BK) {
        float4 av = *(const float4*)(xg + k0);
        float4 bv = *(const float4*)(wg + k0);
        As[acol + 0][arow] = av.x; As[acol + 1][arow] = av.y;
        As[acol + 2][arow] = av.z; As[acol + 3][arow] = av.w;
        Bs[acol + 0][arow] = bv.x; Bs[acol + 1][arow] = bv.y;
        Bs[acol + 2][arow] = bv.z; Bs[acol + 3][arow] = bv.w;
        __syncthreads();

#pragma unroll
        for (int k = 0; k < BK; k++) {
            float4 a0 = *(const float4*)&As[k][trow * 8];
            float4 a1 = *(const float4*)&As[k][trow * 8 + 4];
            float4 b0 = *(const float4*)&Bs[k][tcol * 8];
            float4 b1 = *(const float4*)&Bs[k][tcol * 8 + 4];
            float a[8] = {a0.x, a0.y, a0.z, a0.w, a1.x, a1.y, a1.z, a1.w};
            float b[8] = {b0.x, b0.y, b0.z, b0.w, b1.x, b1.y, b1.z, b1.w};
#pragma unroll
            for (int i = 0; i < 8; i++)
#pragma unroll
                for (int j = 0; j < 8; j++)
                    acc[i][j] = fmaf(a[i], b[j], acc[i][j]);
        }
        __syncthreads();
    }

    const int cbase = blockIdx.x * BN + tcol * 8;
    float bias[8];
#pragma unroll
    for (int j = 0; j < 8; j++) bias[j] = b_ih[cbase + j] + b_hh[cbase + j];

#pragma unroll
    for (int i = 0; i < 8; i++) {
        float* crow = g_gates + (size_t)(blockIdx.y * BM + trow * 8 + i) * GATES + cbase;
        float4 o0, o1;
        o0.x = acc[i][0] + bias[0]; o0.y = acc[i][1] + bias[1];
        o0.z = acc[i][2] + bias[2]; o0.w = acc[i][3] + bias[3];
        o1.x = acc[i][4] + bias[4]; o1.y = acc[i][5] + bias[5];
        o1.z = acc[i][6] + bias[6]; o1.w = acc[i][7] + bias[7];
        *(float4*)(crow)     = o0;
        *(float4*)(crow + 4) = o1;
    }
}

// ======================= Kernel 2: dataflow recurrence ======================
// NO global barrier. Synchronization is the data itself: producer CTA b
// publishes {8 h floats, tag} in one 64B record (single-thread release
// store); consumer warp w of every CTA waits ONLY on the 4 records it needs
// (per-lane acquire of the tag, then the h element on the same line).
// Overwrite safety: tag t+2 can only be published after all CTAs published
// t+1, which requires every warp consumed buffer[t] — skew <= 1 step.
__global__ __launch_bounds__(1024, 1) void lstm_rec_coop(
    const float* __restrict__ Whh, const float* __restrict__ h0,
    const float* __restrict__ c0, float* __restrict__ out)
{
    __shared__ float h_s[HID];
    __shared__ float part_s[32 * 33];
    __shared__ float red_s[32];
    __shared__ float gx_s[2][32];     // double-buffered, prefetched by warp 1

    const int tid  = threadIdx.x;
    const int w    = tid >> 5;
    const int l    = tid & 31;
    const int b    = blockIdx.x;
    const int base = b * 8;
    const int R    = (l >> 3) * HID + base + (l & 7);   // this lane's gate row

    // Load W slice into registers (held for the entire sequence).
    float4 Wreg[8];
    {
        const float4* wrow = (const float4*)(Whh + (size_t)R * HID + w * 32);
#pragma unroll
        for (int k = 0; k < 8; k++) Wreg[k] = wrow[k];
    }

    // Cell state lives in registers of warp 0, lanes 0-7.
    float c_reg = 0.f;
    if (w == 0 && l < 8) c_reg = c0[base + l];

    // Prime gx for step 0.
    if (w == 0) gx_s[0][l] = ldcg_f(&g_gates[(size_t)0 * GATES + R]);

    // This thread's h element = record (tid>>3), float (tid&7).
    const int myrec = tid >> 3;
    const int myj   = tid & 7;

    for (int t = 0; t < T_STEPS; t++) {
        // ---- phase A (warp-local): acquire this warp's 4 h records ----
        float hval;
        if (t == 0) {
            hval = h0[tid];
        } else {
            const HRec* rec = &g_hrec[t & 1][myrec];
            const unsigned want = (unsigned)t;
            int tries = 0;
            for (;;) {
                unsigned tg = ld_acquire_gpu(&rec->tag);   // every lane: own acquire
                if (__all_sync(FULLMASK, tg >= want)) break;
                if (++tries > 4) __nanosleep(32);
            }
            hval = rec->h[myj];        // ordered after this lane's acquire
        }
        h_s[tid] = hval;               // warp-local staging (warp w owns [32w,32w+32))
        if (w == 1 && t + 1 < T_STEPS)
            gx_s[(t + 1) & 1][l] = ldcg_f(&g_gates[(size_t)(t + 1) * GATES + R]);
        __syncwarp();

        // ---- phase B: 32x32 partial dot, 2 accumulators ----
        float acc0 = 0.f, acc1 = 0.f;
        const float4* hv = (const float4*)h_s + w * 8;
#pragma unroll
        for (int k = 0; k < 8; k += 2) {
            float4 h4a = hv[k];
            float4 h4b = hv[k + 1];
            acc0 = fmaf(Wreg[k].x, h4a.x, acc0);
            acc0 = fmaf(Wreg[k].y, h4a.y, acc0);
            acc0 = fmaf(Wreg[k].z, h4a.z, acc0);
            acc0 = fmaf(Wreg[k].w, h4a.w, acc0);
            acc1 = fmaf(Wreg[k + 1].x, h4b.x, acc1);
            acc1 = fmaf(Wreg[k + 1].y, h4b.y, acc1);
            acc1 = fmaf(Wreg[k + 1].z, h4b.z, acc1);
            acc1 = fmaf(Wreg[k + 1].w, h4b.w, acc1);
        }
        part_s[w * 33 + l] = acc0 + acc1;
        __syncthreads();               // B-writes before cross-warp C-reads

        // ---- phase C: transpose reduce: warp w sums local row w ----
        float v = part_s[l * 33 + w];
#pragma unroll
        for (int s = 16; s > 0; s >>= 1)
            v += __shfl_xor_sync(FULLMASK, v, s);
        if (l == 0) red_s[w] = v + gx_s[t & 1][w];
        __syncthreads();               // C-writes before D-reads / next B-writes

        // ---- phase D (warp 0): gates, c/h update, single-thread publish ----
        if (w == 0) {
            float xg_ = red_s[l];
            float nl  = ((l >> 3) == 2) ? tanh_f(xg_) : sigmoid_f(xg_);
            int   j   = l & 7;
            float ii  = __shfl_sync(FULLMASK, nl, j);
            float ff  = __shfl_sync(FULLMASK, nl, j + 8);
            float gg  = __shfl_sync(FULLMASK, nl, j + 16);
            float oo  = __shfl_sync(FULLMASK, nl, j + 24);
            float hnew = 0.f;
            if (l < 8) {
                float c = fmaf(ff, c_reg, ii * gg);
                c_reg   = c;
                hnew    = oo * tanh_f(c);
                out[(size_t)t * HID + base + l] = hnew;
            }
            // Gather the 8 new h values into lane 0 and publish as one record:
            // same-thread ordering (relaxed data stores -> release tag store).
            float p0 = __shfl_sync(FULLMASK, hnew, 0);
            float p1 = __shfl_sync(FULLMASK, hnew, 1);
            float p2 = __shfl_sync(FULLMASK, hnew, 2);
            float p3 = __shfl_sync(FULLMASK, hnew, 3);
            float p4 = __shfl_sync(FULLMASK, hnew, 4);
            float p5 = __shfl_sync(FULLMASK, hnew, 5);
            float p6 = __shfl_sync(FULLMASK, hnew, 6);
            float p7 = __shfl_sync(FULLMASK, hnew, 7);
            if (l == 0 && t + 1 < T_STEPS) {
                HRec* nr = &g_hrec[(t + 1) & 1][b];
                st_relaxed_v4(&nr->h[0], make_float4(p0, p1, p2, p3));
                st_relaxed_v4(&nr->h[4], make_float4(p4, p5, p6, p7));
                st_release_gpu(&nr->tag, (unsigned)(t + 1));
            }
        }
        // no barrier here: phase A of the next step is warp-local, and the
        // __syncthreads after B/C of the next step protect part_s/red_s.
    }
}

// ======================= launch =============================================
extern "C" void kernel_launch(void* const* d_in, const int* in_sizes, int n_in,
                              void* d_out, int out_size)
{
    const float* x    = (const float*)d_in[0];
    const float* Wih  = (const float*)d_in[1];
    const float* Whh  = (const float*)d_in[2];
    const float* b_ih = (const float*)d_in[3];
    const float* b_hh = (const float*)d_in[4];
    const float* h0   = (const float*)d_in[5];
    const float* c0   = (const float*)d_in[6];
    float* out = (float*)d_out;

    dim3 ggrid(GATES / BN, T_STEPS / BM);
    gemm_gates_kernel<<<ggrid, 256>>>(x, Wih, b_ih, b_hh);

    // Cooperative launch: certifies 128-CTA co-residency (loud failure
    // instead of silent non-residency). grid.sync is no longer used.
    void* args[4] = { (void*)&Whh, (void*)&h0, (void*)&c0, (void*)&out };
    cudaLaunchCooperativeKernel((void*)lstm_rec_coop,
                                dim3(REC_GRID, 1, 1), dim3(1024, 1, 1),
                                args, 0, (cudaStream_t)0);
}